// round 1
// baseline (speedup 1.0000x reference)
#include <cuda_runtime.h>
#include <cuda_bf16.h>
#include <cstdint>
#include <cstdio>

#define BQ 2
#define NQ 512
#define DN 128
#define MID 128
#define ZIN 256
#define OUT 256
#define NLAYER 2
#define BIGNEG (-1e6f)

// ---------------- scratch (no allocations allowed) ----------------
__device__ float g_z[BQ*NQ*ZIN];       // layer input z
__device__ float g_msg1[BQ*NQ*MID];
__device__ float g_msg2[BQ*NQ*MID];
__device__ float g_h1[BQ*NQ*OUT];
__device__ float g_msgs[BQ*NQ*MID];
__device__ float g_msgg[BQ*MID];
__device__ unsigned short g_validIdx[BQ*NQ*NQ];
__device__ int g_validCnt[BQ*NQ];

// ---------------- helpers ----------------
__device__ __forceinline__ void cp_async16(void* smem, const void* gmem) {
    unsigned saddr = (unsigned)__cvta_generic_to_shared(smem);
    asm volatile("cp.async.ca.shared.global [%0], [%1], 16;\n" :: "r"(saddr), "l"(gmem));
}
__device__ __forceinline__ void cp_commit() {
    asm volatile("cp.async.commit_group;\n");
}
template <int K>
__device__ __forceinline__ void cp_wait() {
    asm volatile("cp.async.wait_group %0;\n" :: "n"(K));
}

// ---------------- z = concat(node_fts, hidden) ----------------
__global__ void concat_z_kernel(const float* __restrict__ node,
                                const float* __restrict__ hidden,
                                float* __restrict__ z) {
    int idx = blockIdx.x * blockDim.x + threadIdx.x;   // 0 .. B*N*256-1
    int c = idx & (ZIN - 1);
    int row = idx >> 8;
    z[idx] = (c < DN) ? node[row * DN + c] : hidden[row * DN + (c - DN)];
}

// ---------------- compact valid sender lists (one warp per (b,j)) ----------------
__global__ void compact_kernel(const int* __restrict__ adj,
                               unsigned short* __restrict__ idxOut,
                               int* __restrict__ cntOut) {
    int gwarp = (blockIdx.x * blockDim.x + threadIdx.x) >> 5;
    int lane = threadIdx.x & 31;
    if (gwarp >= BQ * NQ) return;
    int b = gwarp / NQ, j = gwarp % NQ;
    int base = gwarp * NQ;
    int cnt = 0;
    for (int it = 0; it < NQ / 32; it++) {
        int i = it * 32 + lane;
        int v = adj[((size_t)(b * NQ + i)) * NQ + j];
        unsigned m = __ballot_sync(0xffffffffu, v != 0);
        if (v != 0) {
            int pos = cnt + __popc(m & ((1u << lane) - 1u));
            idxOut[base + pos] = (unsigned short)i;
        }
        cnt += __popc(m);
    }
    if (lane == 0) cntOut[gwarp] = cnt;
}

// ---------------- msgg = graph_fts @ mg_w + mg_b ----------------
__global__ void msgg_kernel(const float* __restrict__ graph,
                            const float* __restrict__ w,
                            const float* __restrict__ bias,
                            float* __restrict__ out) {
    int b = blockIdx.x;
    int m = threadIdx.x;                 // 128
    __shared__ float gsh[DN];
    gsh[m] = graph[b * DN + m];
    __syncthreads();
    float s = bias[m];
    #pragma unroll 8
    for (int d = 0; d < DN; d++) s += gsh[d] * w[d * MID + m];
    out[b * MID + m] = s;
}

// ---------------- generic small SGEMM: C = A(MxK) @ W(KxN) + bias (+ add, relu) ----------------
__global__ __launch_bounds__(256) void sgemm_bias(
    const float* __restrict__ A, const float* __restrict__ W,
    const float* __restrict__ bias, const float* __restrict__ addsrc,
    float* __restrict__ C, int M, int K, int Ncol, int do_relu) {
    __shared__ float As[16][68];   // [k][m], padded
    __shared__ float Bs[16][64];   // [k][n]
    int tid = threadIdx.x;
    int tx = tid & 15, ty = tid >> 4;
    int rowBase = blockIdx.y * 64;
    int colBase = blockIdx.x * 64;
    float acc[4][4] = {};
    for (int k0 = 0; k0 < K; k0 += 16) {
        {   // A tile 64x16
            int r = tid >> 2;
            int kk = (tid & 3) * 4;
            float4 av = *(const float4*)&A[(size_t)(rowBase + r) * K + k0 + kk];
            As[kk + 0][r] = av.x; As[kk + 1][r] = av.y;
            As[kk + 2][r] = av.z; As[kk + 3][r] = av.w;
        }
        {   // B tile 16x64
            int kr = tid >> 4;
            int cc = (tid & 15) * 4;
            *(float4*)&Bs[kr][cc] =
                *(const float4*)&W[(size_t)(k0 + kr) * Ncol + colBase + cc];
        }
        __syncthreads();
        #pragma unroll
        for (int k = 0; k < 16; k++) {
            float4 a = *(const float4*)&As[k][ty * 4];
            float4 bv = *(const float4*)&Bs[k][tx * 4];
            acc[0][0] += a.x * bv.x; acc[0][1] += a.x * bv.y; acc[0][2] += a.x * bv.z; acc[0][3] += a.x * bv.w;
            acc[1][0] += a.y * bv.x; acc[1][1] += a.y * bv.y; acc[1][2] += a.y * bv.z; acc[1][3] += a.y * bv.w;
            acc[2][0] += a.z * bv.x; acc[2][1] += a.z * bv.y; acc[2][2] += a.z * bv.z; acc[2][3] += a.z * bv.w;
            acc[3][0] += a.w * bv.x; acc[3][1] += a.w * bv.y; acc[3][2] += a.w * bv.z; acc[3][3] += a.w * bv.w;
        }
        __syncthreads();
    }
    #pragma unroll
    for (int i2 = 0; i2 < 4; i2++) {
        int row = rowBase + ty * 4 + i2;
        #pragma unroll
        for (int j2 = 0; j2 < 4; j2++) {
            int col = colBase + tx * 4 + j2;
            float v = acc[i2][j2] + bias[col];
            if (addsrc) v += addsrc[(size_t)row * Ncol + col];
            if (do_relu) v = fmaxf(v, 0.0f);
            C[(size_t)row * Ncol + col] = v;
        }
    }
}

// ---------------- fused edge GEMM + masked max (the big kernel) ----------------
// one CTA per (b,j). 256 threads = 8 warps; thread tile 8(i) x 4(m).
#define TILE_I 64
#define SMEM_ME (MID * MID)                 // 16384 floats
#define SMEM_A  (2 * TILE_I * 128)          // 16384 floats
#define SMEM_RED (8 * MID)                  // 1024 floats
#define SMEM_B_BYTES ((SMEM_ME + SMEM_A + SMEM_RED) * 4 + NQ * 2)

__device__ __forceinline__ void issue_tile_load(
    const float* __restrict__ edge, const unsigned short* idx_sh,
    float* dstbase, int t, int cnt, int b, int j, int tid) {
    int r = tid >> 2;                 // 0..63 (4 threads per row)
    int gi = t * TILE_I + r;
    if (gi >= cnt) gi = cnt - 1;      // clamp (safe: only called when cnt>0)
    int i = idx_sh[gi];
    const float* src = edge + (((size_t)(b * NQ + i)) * NQ + j) * 128;
    float* dst = dstbase + r * 128;
    int f0 = tid & 3;
    #pragma unroll
    for (int u = 0; u < 8; u++) {
        int f = f0 + u * 4;           // float4 index within row
        cp_async16(dst + f * 4, src + f * 4);
    }
}

__global__ __launch_bounds__(256, 1) void edge_max_kernel(
    const float* __restrict__ edge, const float* __restrict__ me_w,
    const float* __restrict__ me_b,
    const float* __restrict__ msg1, const float* __restrict__ msg2,
    const float* __restrict__ msgg,
    const unsigned short* __restrict__ validIdx,
    const int* __restrict__ validCnt,
    float* __restrict__ msgs) {
    extern __shared__ float sh[];
    float* me_sh = sh;                               // 128x128, [k][m]
    float* A_sh = sh + SMEM_ME;                      // 2 x 64 x 128, [i][k]
    float* red = A_sh + SMEM_A;                      // 8 x 128
    unsigned short* idx_sh = (unsigned short*)(red + SMEM_RED);

    int tid = threadIdx.x;
    int tx = tid & 31;        // m-group (4 cols)
    int ty = tid >> 5;        // warp id = i-group
    int bj = blockIdx.x;
    int b = bj >> 9;
    int j = bj & (NQ - 1);
    int cnt = validCnt[bj];

    // me_w -> shared (coalesced float4)
    {
        const float4* src = (const float4*)me_w;
        float4* dst = (float4*)me_sh;
        #pragma unroll
        for (int u = 0; u < 16; u++) dst[tid + u * 256] = src[tid + u * 256];
    }
    // valid index list -> shared
    for (int p = tid; p < cnt; p += 256) idx_sh[p] = validIdx[bj * NQ + p];
    __syncthreads();

    float vmax[4] = {-INFINITY, -INFINITY, -INFINITY, -INFINITY};
    int ntile = (cnt + TILE_I - 1) >> 6;

    if (ntile > 0) { issue_tile_load(edge, idx_sh, A_sh, 0, cnt, b, j, tid); cp_commit(); }

    for (int t = 0; t < ntile; t++) {
        int buf = t & 1;
        if (t + 1 < ntile) {
            issue_tile_load(edge, idx_sh, A_sh + (buf ^ 1) * TILE_I * 128, t + 1, cnt, b, j, tid);
            cp_commit();
            cp_wait<1>();
        } else {
            cp_wait<0>();
        }
        __syncthreads();

        float acc[8][4];
        #pragma unroll
        for (int u = 0; u < 8; u++) { acc[u][0]=0.f; acc[u][1]=0.f; acc[u][2]=0.f; acc[u][3]=0.f; }

        const float* Ab = A_sh + buf * TILE_I * 128;
        #pragma unroll 4
        for (int k = 0; k < 128; k++) {
            float4 bv = *(const float4*)&me_sh[k * MID + tx * 4];
            #pragma unroll
            for (int u = 0; u < 8; u++) {
                float a = Ab[(ty + u * 8) * 128 + k];
                acc[u][0] += a * bv.x;
                acc[u][1] += a * bv.y;
                acc[u][2] += a * bv.z;
                acc[u][3] += a * bv.w;
            }
        }

        // epilogue: add msg2[i], fold into running max
        #pragma unroll
        for (int u = 0; u < 8; u++) {
            int gi = t * TILE_I + ty + u * 8;
            if (gi < cnt) {
                int i = idx_sh[gi];
                float4 m2 = *(const float4*)&msg2[((size_t)(b * NQ + i)) * MID + tx * 4];
                vmax[0] = fmaxf(vmax[0], acc[u][0] + m2.x);
                vmax[1] = fmaxf(vmax[1], acc[u][1] + m2.y);
                vmax[2] = fmaxf(vmax[2], acc[u][2] + m2.z);
                vmax[3] = fmaxf(vmax[3], acc[u][3] + m2.w);
            }
        }
        __syncthreads();   // protect A_sh buffer reuse by next prefetch
    }

    // cross-warp max reduce
    *(float4*)&red[ty * MID + tx * 4] = make_float4(vmax[0], vmax[1], vmax[2], vmax[3]);
    __syncthreads();
    if (tid < MID) {
        int m = tid;
        float v = red[m];
        #pragma unroll
        for (int r = 1; r < 8; r++) v = fmaxf(v, red[r * MID + m]);
        float outv = (cnt > 0)
            ? (msg1[(size_t)bj * MID + m] + msgg[b * MID + m] + me_b[m] + v)
            : BIGNEG;
        msgs[(size_t)bj * MID + m] = outv;
    }
}

// ---------------- launch ----------------
extern "C" void kernel_launch(void* const* d_in, const int* in_sizes, int n_in,
                              void* d_out, int out_size) {
    const float* node   = (const float*)d_in[0];
    const float* edge   = (const float*)d_in[1];
    const float* graph  = (const float*)d_in[2];
    const float* hidden = (const float*)d_in[3];
    const int*   adj    = (const int*)d_in[4];
    const float* m1_w = (const float*)d_in[5];
    const float* m1_b = (const float*)d_in[6];
    const float* m2_w = (const float*)d_in[7];
    const float* m2_b = (const float*)d_in[8];
    const float* me_w = (const float*)d_in[9];
    const float* me_b = (const float*)d_in[10];
    const float* mg_w = (const float*)d_in[11];
    const float* mg_b = (const float*)d_in[12];
    const float* o1_w = (const float*)d_in[13];
    const float* o1_b = (const float*)d_in[14];
    const float* o2_w = (const float*)d_in[15];
    const float* o2_b = (const float*)d_in[16];

    float *z, *msg1, *msg2, *h1, *msgs, *msgg;
    unsigned short* vidx;
    int* vcnt;
    cudaGetSymbolAddress((void**)&z, g_z);
    cudaGetSymbolAddress((void**)&msg1, g_msg1);
    cudaGetSymbolAddress((void**)&msg2, g_msg2);
    cudaGetSymbolAddress((void**)&h1, g_h1);
    cudaGetSymbolAddress((void**)&msgs, g_msgs);
    cudaGetSymbolAddress((void**)&msgg, g_msgg);
    cudaGetSymbolAddress((void**)&vidx, g_validIdx);
    cudaGetSymbolAddress((void**)&vcnt, g_validCnt);

    cudaFuncSetAttribute(edge_max_kernel,
                         cudaFuncAttributeMaxDynamicSharedMemorySize, SMEM_B_BYTES);

    concat_z_kernel<<<(BQ * NQ * ZIN) / 256, 256>>>(node, hidden, z);
    compact_kernel<<<(BQ * NQ) / 8, 256>>>(adj, vidx, vcnt);

    for (int l = 0; l < NLAYER; l++) {
        sgemm_bias<<<dim3(MID / 64, (BQ * NQ) / 64), 256>>>(
            z, m1_w + (size_t)l * ZIN * MID, m1_b + l * MID, nullptr, msg1,
            BQ * NQ, ZIN, MID, 0);
        sgemm_bias<<<dim3(MID / 64, (BQ * NQ) / 64), 256>>>(
            z, m2_w + (size_t)l * ZIN * MID, m2_b + l * MID, nullptr, msg2,
            BQ * NQ, ZIN, MID, 0);
        sgemm_bias<<<dim3(OUT / 64, (BQ * NQ) / 64), 256>>>(
            z, o1_w + (size_t)l * ZIN * OUT, o1_b + l * OUT, nullptr, h1,
            BQ * NQ, ZIN, OUT, 0);
        msgg_kernel<<<BQ, MID>>>(graph, mg_w + (size_t)l * DN * MID, mg_b + l * MID, msgg);

        edge_max_kernel<<<BQ * NQ, 256, SMEM_B_BYTES>>>(
            edge, me_w + (size_t)l * DN * MID, me_b + l * MID,
            msg1, msg2, msgg, vidx, vcnt, msgs);

        float* dest = (l == NLAYER - 1) ? (float*)d_out : z;
        sgemm_bias<<<dim3(OUT / 64, (BQ * NQ) / 64), 256>>>(
            msgs, o2_w + (size_t)l * MID * OUT, o2_b + l * OUT, h1, dest,
            BQ * NQ, MID, OUT, 1);
    }
}

// round 2
// speedup vs baseline: 1.0021x; 1.0021x over previous
#include <cuda_runtime.h>
#include <cuda_bf16.h>
#include <cstdint>
#include <cstdio>

#define BQ 2
#define NQ 512
#define DN 128
#define MID 128
#define ZIN 256
#define OUT 256
#define NLAYER 2
#define BIGNEG (-1e6f)

// ---------------- scratch (no allocations allowed) ----------------
__device__ float g_z[BQ*NQ*ZIN];       // layer input z
__device__ float g_msg1[BQ*NQ*MID];
__device__ float g_msg2[BQ*NQ*MID];
__device__ float g_h1[BQ*NQ*OUT];
__device__ float g_msgs[BQ*NQ*MID];
__device__ float g_msgg[BQ*MID];
__device__ unsigned short g_validIdx[BQ*NQ*NQ];
__device__ int g_validCnt[BQ*NQ];

// ---------------- helpers ----------------
__device__ __forceinline__ void cp_async16(void* smem, const void* gmem) {
    unsigned saddr = (unsigned)__cvta_generic_to_shared(smem);
    asm volatile("cp.async.ca.shared.global [%0], [%1], 16;\n" :: "r"(saddr), "l"(gmem));
}
__device__ __forceinline__ void cp_commit() {
    asm volatile("cp.async.commit_group;\n");
}
template <int K>
__device__ __forceinline__ void cp_wait() {
    asm volatile("cp.async.wait_group %0;\n" :: "n"(K));
}

// ---------------- z = concat(node_fts, hidden) ----------------
__global__ void concat_z_kernel(const float* __restrict__ node,
                                const float* __restrict__ hidden,
                                float* __restrict__ z) {
    int idx = blockIdx.x * blockDim.x + threadIdx.x;   // 0 .. B*N*256-1
    int c = idx & (ZIN - 1);
    int row = idx >> 8;
    z[idx] = (c < DN) ? node[row * DN + c] : hidden[row * DN + (c - DN)];
}

// ---------------- compact valid sender lists (one warp per (b,j)) ----------------
__global__ void compact_kernel(const int* __restrict__ adj,
                               unsigned short* __restrict__ idxOut,
                               int* __restrict__ cntOut) {
    int gwarp = (blockIdx.x * blockDim.x + threadIdx.x) >> 5;
    int lane = threadIdx.x & 31;
    if (gwarp >= BQ * NQ) return;
    int b = gwarp / NQ, j = gwarp % NQ;
    int base = gwarp * NQ;
    int cnt = 0;
    for (int it = 0; it < NQ / 32; it++) {
        int i = it * 32 + lane;
        int v = adj[((size_t)(b * NQ + i)) * NQ + j];
        unsigned m = __ballot_sync(0xffffffffu, v != 0);
        if (v != 0) {
            int pos = cnt + __popc(m & ((1u << lane) - 1u));
            idxOut[base + pos] = (unsigned short)i;
        }
        cnt += __popc(m);
    }
    if (lane == 0) cntOut[gwarp] = cnt;
}

// ---------------- msgg = graph_fts @ mg_w + mg_b ----------------
__global__ void msgg_kernel(const float* __restrict__ graph,
                            const float* __restrict__ w,
                            const float* __restrict__ bias,
                            float* __restrict__ out) {
    int b = blockIdx.x;
    int m = threadIdx.x;                 // 128
    __shared__ float gsh[DN];
    gsh[m] = graph[b * DN + m];
    __syncthreads();
    float s = bias[m];
    #pragma unroll 8
    for (int d = 0; d < DN; d++) s += gsh[d] * w[d * MID + m];
    out[b * MID + m] = s;
}

// ---------------- generic small SGEMM: C = A(MxK) @ W(KxN) + bias (+ add, relu) ----------------
__global__ __launch_bounds__(256) void sgemm_bias(
    const float* __restrict__ A, const float* __restrict__ W,
    const float* __restrict__ bias, const float* __restrict__ addsrc,
    float* __restrict__ C, int M, int K, int Ncol, int do_relu) {
    __shared__ float As[16][68];   // [k][m], padded
    __shared__ float Bs[16][64];   // [k][n]
    int tid = threadIdx.x;
    int tx = tid & 15, ty = tid >> 4;
    int rowBase = blockIdx.y * 64;
    int colBase = blockIdx.x * 64;
    float acc[4][4] = {};
    for (int k0 = 0; k0 < K; k0 += 16) {
        {   // A tile 64x16
            int r = tid >> 2;
            int kk = (tid & 3) * 4;
            float4 av = *(const float4*)&A[(size_t)(rowBase + r) * K + k0 + kk];
            As[kk + 0][r] = av.x; As[kk + 1][r] = av.y;
            As[kk + 2][r] = av.z; As[kk + 3][r] = av.w;
        }
        {   // B tile 16x64
            int kr = tid >> 4;
            int cc = (tid & 15) * 4;
            *(float4*)&Bs[kr][cc] =
                *(const float4*)&W[(size_t)(k0 + kr) * Ncol + colBase + cc];
        }
        __syncthreads();
        #pragma unroll
        for (int k = 0; k < 16; k++) {
            float4 a = *(const float4*)&As[k][ty * 4];
            float4 bv = *(const float4*)&Bs[k][tx * 4];
            acc[0][0] += a.x * bv.x; acc[0][1] += a.x * bv.y; acc[0][2] += a.x * bv.z; acc[0][3] += a.x * bv.w;
            acc[1][0] += a.y * bv.x; acc[1][1] += a.y * bv.y; acc[1][2] += a.y * bv.z; acc[1][3] += a.y * bv.w;
            acc[2][0] += a.z * bv.x; acc[2][1] += a.z * bv.y; acc[2][2] += a.z * bv.z; acc[2][3] += a.z * bv.w;
            acc[3][0] += a.w * bv.x; acc[3][1] += a.w * bv.y; acc[3][2] += a.w * bv.z; acc[3][3] += a.w * bv.w;
        }
        __syncthreads();
    }
    #pragma unroll
    for (int i2 = 0; i2 < 4; i2++) {
        int row = rowBase + ty * 4 + i2;
        #pragma unroll
        for (int j2 = 0; j2 < 4; j2++) {
            int col = colBase + tx * 4 + j2;
            float v = acc[i2][j2] + bias[col];
            if (addsrc) v += addsrc[(size_t)row * Ncol + col];
            if (do_relu) v = fmaxf(v, 0.0f);
            C[(size_t)row * Ncol + col] = v;
        }
    }
}

// ---------------- fused edge GEMM + masked max (the big kernel) ----------------
// one CTA per (b,j). 256 threads = 8 warps; thread tile 8(i) x 4(m).
#define TILE_I 64
#define SMEM_ME (MID * MID)                 // 16384 floats
#define SMEM_A  (2 * TILE_I * 128)          // 16384 floats
#define SMEM_RED (8 * MID)                  // 1024 floats
#define SMEM_B_BYTES ((SMEM_ME + SMEM_A + SMEM_RED) * 4 + NQ * 2)

__device__ __forceinline__ void issue_tile_load(
    const float* __restrict__ edge, const unsigned short* idx_sh,
    float* dstbase, int t, int cnt, int b, int j, int tid) {
    int r = tid >> 2;                 // 0..63 (4 threads per row)
    int gi = t * TILE_I + r;
    if (gi >= cnt) gi = cnt - 1;      // clamp (safe: only called when cnt>0)
    int i = idx_sh[gi];
    const float* src = edge + (((size_t)(b * NQ + i)) * NQ + j) * 128;
    float* dst = dstbase + r * 128;
    int f0 = tid & 3;
    #pragma unroll
    for (int u = 0; u < 8; u++) {
        int f = f0 + u * 4;           // float4 index within row
        cp_async16(dst + f * 4, src + f * 4);
    }
}

__global__ __launch_bounds__(256, 1) void edge_max_kernel(
    const float* __restrict__ edge, const float* __restrict__ me_w,
    const float* __restrict__ me_b,
    const float* __restrict__ msg1, const float* __restrict__ msg2,
    const float* __restrict__ msgg,
    const unsigned short* __restrict__ validIdx,
    const int* __restrict__ validCnt,
    float* __restrict__ msgs) {
    extern __shared__ float sh[];
    float* me_sh = sh;                               // 128x128, [k][m]
    float* A_sh = sh + SMEM_ME;                      // 2 x 64 x 128, [i][k]
    float* red = A_sh + SMEM_A;                      // 8 x 128
    unsigned short* idx_sh = (unsigned short*)(red + SMEM_RED);

    int tid = threadIdx.x;
    int tx = tid & 31;        // m-group (4 cols)
    int ty = tid >> 5;        // warp id = i-group
    int bj = blockIdx.x;
    int b = bj >> 9;
    int j = bj & (NQ - 1);
    int cnt = validCnt[bj];

    // me_w -> shared (coalesced float4)
    {
        const float4* src = (const float4*)me_w;
        float4* dst = (float4*)me_sh;
        #pragma unroll
        for (int u = 0; u < 16; u++) dst[tid + u * 256] = src[tid + u * 256];
    }
    // valid index list -> shared
    for (int p = tid; p < cnt; p += 256) idx_sh[p] = validIdx[bj * NQ + p];
    __syncthreads();

    float vmax[4] = {-INFINITY, -INFINITY, -INFINITY, -INFINITY};
    int ntile = (cnt + TILE_I - 1) >> 6;

    if (ntile > 0) { issue_tile_load(edge, idx_sh, A_sh, 0, cnt, b, j, tid); cp_commit(); }

    for (int t = 0; t < ntile; t++) {
        int buf = t & 1;
        if (t + 1 < ntile) {
            issue_tile_load(edge, idx_sh, A_sh + (buf ^ 1) * TILE_I * 128, t + 1, cnt, b, j, tid);
            cp_commit();
            cp_wait<1>();
        } else {
            cp_wait<0>();
        }
        __syncthreads();

        float acc[8][4];
        #pragma unroll
        for (int u = 0; u < 8; u++) { acc[u][0]=0.f; acc[u][1]=0.f; acc[u][2]=0.f; acc[u][3]=0.f; }

        const float* Ab = A_sh + buf * TILE_I * 128;
        #pragma unroll 4
        for (int k = 0; k < 128; k++) {
            float4 bv = *(const float4*)&me_sh[k * MID + tx * 4];
            #pragma unroll
            for (int u = 0; u < 8; u++) {
                float a = Ab[(ty + u * 8) * 128 + k];
                acc[u][0] += a * bv.x;
                acc[u][1] += a * bv.y;
                acc[u][2] += a * bv.z;
                acc[u][3] += a * bv.w;
            }
        }

        // epilogue: add msg2[i], fold into running max
        #pragma unroll
        for (int u = 0; u < 8; u++) {
            int gi = t * TILE_I + ty + u * 8;
            if (gi < cnt) {
                int i = idx_sh[gi];
                float4 m2 = *(const float4*)&msg2[((size_t)(b * NQ + i)) * MID + tx * 4];
                vmax[0] = fmaxf(vmax[0], acc[u][0] + m2.x);
                vmax[1] = fmaxf(vmax[1], acc[u][1] + m2.y);
                vmax[2] = fmaxf(vmax[2], acc[u][2] + m2.z);
                vmax[3] = fmaxf(vmax[3], acc[u][3] + m2.w);
            }
        }
        __syncthreads();   // protect A_sh buffer reuse by next prefetch
    }

    // cross-warp max reduce
    *(float4*)&red[ty * MID + tx * 4] = make_float4(vmax[0], vmax[1], vmax[2], vmax[3]);
    __syncthreads();
    if (tid < MID) {
        int m = tid;
        float v = red[m];
        #pragma unroll
        for (int r = 1; r < 8; r++) v = fmaxf(v, red[r * MID + m]);
        float outv = (cnt > 0)
            ? (msg1[(size_t)bj * MID + m] + msgg[b * MID + m] + me_b[m] + v)
            : BIGNEG;
        msgs[(size_t)bj * MID + m] = outv;
    }
}

// ---------------- launch ----------------
extern "C" void kernel_launch(void* const* d_in, const int* in_sizes, int n_in,
                              void* d_out, int out_size) {
    const float* node   = (const float*)d_in[0];
    const float* edge   = (const float*)d_in[1];
    const float* graph  = (const float*)d_in[2];
    const float* hidden = (const float*)d_in[3];
    const int*   adj    = (const int*)d_in[4];
    const float* m1_w = (const float*)d_in[5];
    const float* m1_b = (const float*)d_in[6];
    const float* m2_w = (const float*)d_in[7];
    const float* m2_b = (const float*)d_in[8];
    const float* me_w = (const float*)d_in[9];
    const float* me_b = (const float*)d_in[10];
    const float* mg_w = (const float*)d_in[11];
    const float* mg_b = (const float*)d_in[12];
    const float* o1_w = (const float*)d_in[13];
    const float* o1_b = (const float*)d_in[14];
    const float* o2_w = (const float*)d_in[15];
    const float* o2_b = (const float*)d_in[16];

    float *z, *msg1, *msg2, *h1, *msgs, *msgg;
    unsigned short* vidx;
    int* vcnt;
    cudaGetSymbolAddress((void**)&z, g_z);
    cudaGetSymbolAddress((void**)&msg1, g_msg1);
    cudaGetSymbolAddress((void**)&msg2, g_msg2);
    cudaGetSymbolAddress((void**)&h1, g_h1);
    cudaGetSymbolAddress((void**)&msgs, g_msgs);
    cudaGetSymbolAddress((void**)&msgg, g_msgg);
    cudaGetSymbolAddress((void**)&vidx, g_validIdx);
    cudaGetSymbolAddress((void**)&vcnt, g_validCnt);

    cudaFuncSetAttribute(edge_max_kernel,
                         cudaFuncAttributeMaxDynamicSharedMemorySize, SMEM_B_BYTES);

    concat_z_kernel<<<(BQ * NQ * ZIN) / 256, 256>>>(node, hidden, z);
    compact_kernel<<<(BQ * NQ) / 8, 256>>>(adj, vidx, vcnt);

    for (int l = 0; l < NLAYER; l++) {
        sgemm_bias<<<dim3(MID / 64, (BQ * NQ) / 64), 256>>>(
            z, m1_w + (size_t)l * ZIN * MID, m1_b + l * MID, nullptr, msg1,
            BQ * NQ, ZIN, MID, 0);
        sgemm_bias<<<dim3(MID / 64, (BQ * NQ) / 64), 256>>>(
            z, m2_w + (size_t)l * ZIN * MID, m2_b + l * MID, nullptr, msg2,
            BQ * NQ, ZIN, MID, 0);
        sgemm_bias<<<dim3(OUT / 64, (BQ * NQ) / 64), 256>>>(
            z, o1_w + (size_t)l * ZIN * OUT, o1_b + l * OUT, nullptr, h1,
            BQ * NQ, ZIN, OUT, 0);
        msgg_kernel<<<BQ, MID>>>(graph, mg_w + (size_t)l * DN * MID, mg_b + l * MID, msgg);

        edge_max_kernel<<<BQ * NQ, 256, SMEM_B_BYTES>>>(
            edge, me_w + (size_t)l * DN * MID, me_b + l * MID,
            msg1, msg2, msgg, vidx, vcnt, msgs);

        float* dest = (l == NLAYER - 1) ? (float*)d_out : z;
        sgemm_bias<<<dim3(OUT / 64, (BQ * NQ) / 64), 256>>>(
            msgs, o2_w + (size_t)l * MID * OUT, o2_b + l * OUT, h1, dest,
            BQ * NQ, MID, OUT, 1);
    }
}

// round 4
// speedup vs baseline: 1.8015x; 1.7977x over previous
#include <cuda_runtime.h>
#include <cuda_bf16.h>
#include <cstdint>

#define BQ 2
#define NQ 512
#define DN 128
#define MID 128
#define ZIN 256
#define OUT 256
#define NLAYER 2
#define BIGNEG (-1e6f)

// ---------------- scratch ----------------
__device__ float g_z[BQ*NQ*ZIN];
__device__ float g_msg1[BQ*NQ*MID];
__device__ float g_msg2[BQ*NQ*MID];
__device__ float g_h1[BQ*NQ*OUT];
__device__ float g_msgs[BQ*NQ*MID];
__device__ float g_msgg[BQ*MID];
__device__ unsigned short g_validIdx[BQ*NQ*NQ];
__device__ int g_validCnt[BQ*NQ];
__device__ __align__(16) __nv_bfloat16 g_wt_hi[NLAYER*MID*DN];  // me_w^T hi [l][m][d]
__device__ __align__(16) __nv_bfloat16 g_wt_lo[NLAYER*MID*DN];

// ---------------- helpers ----------------
__device__ __forceinline__ unsigned smem_u32(const void* p) {
    return (unsigned)__cvta_generic_to_shared(p);
}
__device__ __forceinline__ void cp_async16(void* s, const void* g) {
    asm volatile("cp.async.ca.shared.global [%0], [%1], 16;" :: "r"(smem_u32(s)), "l"(g));
}
__device__ __forceinline__ void cp_async16u(unsigned s, const void* g) {
    asm volatile("cp.async.ca.shared.global [%0], [%1], 16;" :: "r"(s), "l"(g));
}
__device__ __forceinline__ void cp_commit() { asm volatile("cp.async.commit_group;"); }
template <int K>
__device__ __forceinline__ void cp_wait() { asm volatile("cp.async.wait_group %0;" :: "n"(K)); }

__device__ __forceinline__ void ldmx4(unsigned* a, unsigned addr) {
    asm volatile("ldmatrix.sync.aligned.m8n8.x4.shared.b16 {%0,%1,%2,%3}, [%4];"
                 : "=r"(a[0]), "=r"(a[1]), "=r"(a[2]), "=r"(a[3]) : "r"(addr));
}
__device__ __forceinline__ void mma16816(float* d, const unsigned* a, const unsigned* b) {
    asm volatile(
        "mma.sync.aligned.m16n8k16.row.col.f32.bf16.bf16.f32 "
        "{%0,%1,%2,%3}, {%4,%5,%6,%7}, {%8,%9}, {%0,%1,%2,%3};"
        : "+f"(d[0]), "+f"(d[1]), "+f"(d[2]), "+f"(d[3])
        : "r"(a[0]), "r"(a[1]), "r"(a[2]), "r"(a[3]), "r"(b[0]), "r"(b[1]));
}
__device__ __forceinline__ void sts128(unsigned a, unsigned x, unsigned y, unsigned z, unsigned w) {
    asm volatile("st.shared.v4.b32 [%0], {%1,%2,%3,%4};" :: "r"(a), "r"(x), "r"(y), "r"(z), "r"(w) : "memory");
}
__device__ __forceinline__ unsigned pack2(__nv_bfloat162 v) { return *(unsigned*)&v; }

// ---------------- prep kernels ----------------
__global__ void concat_z_kernel(const float* __restrict__ node,
                                const float* __restrict__ hidden,
                                float* __restrict__ z) {
    int idx = blockIdx.x * blockDim.x + threadIdx.x;
    int c = idx & (ZIN - 1);
    int row = idx >> 8;
    z[idx] = (c < DN) ? node[row * DN + c] : hidden[row * DN + (c - DN)];
}

__global__ void compact_kernel(const int* __restrict__ adj,
                               unsigned short* __restrict__ idxOut,
                               int* __restrict__ cntOut) {
    int gwarp = (blockIdx.x * blockDim.x + threadIdx.x) >> 5;
    int lane = threadIdx.x & 31;
    if (gwarp >= BQ * NQ) return;
    int b = gwarp / NQ, j = gwarp % NQ;
    int base = gwarp * NQ;
    int cnt = 0;
    for (int it = 0; it < NQ / 32; it++) {
        int i = it * 32 + lane;
        int v = adj[((size_t)(b * NQ + i)) * NQ + j];
        unsigned mm = __ballot_sync(0xffffffffu, v != 0);
        if (v != 0) idxOut[base + cnt + __popc(mm & ((1u << lane) - 1u))] = (unsigned short)i;
        cnt += __popc(mm);
    }
    if (lane == 0) cntOut[gwarp] = cnt;
}

__global__ void prep_wt_kernel(const float* __restrict__ me_w,
                               __nv_bfloat16* __restrict__ wt_hi,
                               __nv_bfloat16* __restrict__ wt_lo) {
    int idx = blockIdx.x * blockDim.x + threadIdx.x;   // L*128*128
    int l = idx >> 14;
    int r = idx & 16383;
    int m = r >> 7, d = r & 127;
    float v = me_w[(size_t)l * DN * MID + d * MID + m];
    __nv_bfloat16 h = __float2bfloat16_rn(v);
    wt_hi[idx] = h;
    wt_lo[idx] = __float2bfloat16_rn(v - __bfloat162float(h));
}

__global__ void msgg_kernel(const float* __restrict__ graph,
                            const float* __restrict__ w,
                            const float* __restrict__ bias,
                            float* __restrict__ out) {
    int b = blockIdx.x;
    int m = threadIdx.x;
    __shared__ float gsh[DN];
    gsh[m] = graph[b * DN + m];
    __syncthreads();
    float s = bias[m];
    #pragma unroll 8
    for (int d = 0; d < DN; d++) s += gsh[d] * w[d * MID + m];
    out[b * MID + m] = s;
}

// ---------------- pipelined 64x64 fp32 GEMM body (small GEMMs) ----------------
__device__ __forceinline__ void gemm64(
    const float* __restrict__ A, const float* __restrict__ W,
    const float* __restrict__ bias, const float* __restrict__ addsrc,
    float* __restrict__ C, int K, int Nw, int rowBase, int cb, int relu,
    float (&As)[2][64][20], float (&Bs)[2][16][64]) {
    int tid = threadIdx.x;
    int tx = tid & 15, ty = tid >> 4;
    int ar = tid >> 2, ak = (tid & 3) * 4;
    int bk = tid >> 4, bc = (tid & 15) * 4;
    float acc[4][4] = {};
    int nkt = K >> 4;
    cp_async16(&As[0][ar][ak], &A[(size_t)(rowBase + ar) * K + ak]);
    cp_async16(&Bs[0][bk][bc], &W[(size_t)bk * Nw + cb + bc]);
    cp_commit();
    for (int kt = 0; kt < nkt; kt++) {
        int buf = kt & 1;
        if (kt + 1 < nkt) {
            cp_async16(&As[buf ^ 1][ar][ak], &A[(size_t)(rowBase + ar) * K + (kt + 1) * 16 + ak]);
            cp_async16(&Bs[buf ^ 1][bk][bc], &W[(size_t)((kt + 1) * 16 + bk) * Nw + cb + bc]);
            cp_commit();
            cp_wait<1>();
        } else {
            cp_wait<0>();
        }
        __syncthreads();
        #pragma unroll
        for (int k = 0; k < 16; k++) {
            float a0 = As[buf][ty * 4 + 0][k];
            float a1 = As[buf][ty * 4 + 1][k];
            float a2 = As[buf][ty * 4 + 2][k];
            float a3 = As[buf][ty * 4 + 3][k];
            float4 bv = *(const float4*)&Bs[buf][k][tx * 4];
            acc[0][0] += a0 * bv.x; acc[0][1] += a0 * bv.y; acc[0][2] += a0 * bv.z; acc[0][3] += a0 * bv.w;
            acc[1][0] += a1 * bv.x; acc[1][1] += a1 * bv.y; acc[1][2] += a1 * bv.z; acc[1][3] += a1 * bv.w;
            acc[2][0] += a2 * bv.x; acc[2][1] += a2 * bv.y; acc[2][2] += a2 * bv.z; acc[2][3] += a2 * bv.w;
            acc[3][0] += a3 * bv.x; acc[3][1] += a3 * bv.y; acc[3][2] += a3 * bv.z; acc[3][3] += a3 * bv.w;
        }
        __syncthreads();
    }
    #pragma unroll
    for (int i2 = 0; i2 < 4; i2++) {
        int row = rowBase + ty * 4 + i2;
        #pragma unroll
        for (int j2 = 0; j2 < 4; j2++) {
            int col = cb + tx * 4 + j2;
            float v = acc[i2][j2] + bias[col];
            if (addsrc) v += addsrc[(size_t)row * Nw + col];
            if (relu) v = fmaxf(v, 0.0f);
            C[(size_t)row * Nw + col] = v;
        }
    }
}

__global__ __launch_bounds__(256) void zmm_kernel(
    const float* __restrict__ z,
    const float* __restrict__ m1_w, const float* __restrict__ m1_b,
    const float* __restrict__ m2_w, const float* __restrict__ m2_b,
    const float* __restrict__ o1_w, const float* __restrict__ o1_b,
    float* __restrict__ msg1, float* __restrict__ msg2, float* __restrict__ h1) {
    __shared__ float As[2][64][20];
    __shared__ float Bs[2][16][64];
    int bx = blockIdx.x, rb = blockIdx.y * 64;
    if (bx < 2)      gemm64(z, m1_w, m1_b, nullptr, msg1, 256, 128, rb, bx * 64, 0, As, Bs);
    else if (bx < 4) gemm64(z, m2_w, m2_b, nullptr, msg2, 256, 128, rb, (bx - 2) * 64, 0, As, Bs);
    else             gemm64(z, o1_w, o1_b, nullptr, h1, 256, 256, rb, (bx - 4) * 64, 0, As, Bs);
}

__global__ __launch_bounds__(256) void o2_kernel(
    const float* __restrict__ msgs, const float* __restrict__ W,
    const float* __restrict__ bias, const float* __restrict__ h1,
    float* __restrict__ C) {
    __shared__ float As[2][64][20];
    __shared__ float Bs[2][16][64];
    gemm64(msgs, W, bias, h1, C, 128, 256, blockIdx.y * 64, blockIdx.x * 64, 1, As, Bs);
}

// ---------------- fused edge GEMM + masked max via mma.sync (bf16 x3 split) ----------------
// smem: [0,32768) E_hi (or W_hi staging), [32768,65536) E_lo (or W_lo), [65536,66560) idx
#define EDGE_SMEM 66560

__global__ __launch_bounds__(256, 1) void edge_mma_kernel(
    const float* __restrict__ edge,
    const __nv_bfloat16* __restrict__ wt_hi, const __nv_bfloat16* __restrict__ wt_lo,
    const float* __restrict__ me_b,
    const float* __restrict__ msg1, const float* __restrict__ msg2,
    const float* __restrict__ msgg,
    const unsigned short* __restrict__ validIdx, const int* __restrict__ validCnt,
    float* __restrict__ msgs) {
    extern __shared__ char smraw[];
    unsigned sbase = smem_u32(smraw);
    unsigned short* idx_sh = (unsigned short*)(smraw + 65536);

    int tid = threadIdx.x;
    int w = tid >> 5, l = tid & 31;

    // ---- stage W hi/lo (32KB each), then load B fragments into registers ----
    #pragma unroll
    for (int u = 0; u < 8; u++) {
        int q = tid + u * 256;                 // 16B unit index, 0..2047
        cp_async16u(sbase + q * 16, (const char*)wt_hi + q * 16);
        cp_async16u(sbase + 32768 + q * 16, (const char*)wt_lo + q * 16);
    }
    cp_commit();
    cp_wait<0>();
    __syncthreads();

    // B fragment: lane l holds W[n][k..k+1] with n = w*16 + nt*8 + l/4, k = kt*16 + (l%4)*2 (+8 for reg1)
    unsigned bhi[8][2][2], blo[8][2][2];
    {
        int nl = l >> 2, k4 = (l & 3) * 4;
        #pragma unroll
        for (int nt = 0; nt < 2; nt++) {
            unsigned roff = (unsigned)(w * 16 + nt * 8 + nl) * 256u + (unsigned)k4;
            #pragma unroll
            for (int kt = 0; kt < 8; kt++) {
                bhi[kt][nt][0] = *(const unsigned*)(smraw + roff + kt * 32);
                bhi[kt][nt][1] = *(const unsigned*)(smraw + roff + kt * 32 + 16);
                blo[kt][nt][0] = *(const unsigned*)(smraw + 32768 + roff + kt * 32);
                blo[kt][nt][1] = *(const unsigned*)(smraw + 32768 + roff + kt * 32 + 16);
            }
        }
    }
    __syncthreads();   // W smem now reusable as E tile

    int cvt_r = tid >> 1, cvt_h = tid & 1;     // convert: 2 threads per row
    unsigned arow = (unsigned)(l & 15);        // ldmatrix lane row
    unsigned akoff = (unsigned)(l >> 4);       // ldmatrix k-half select

    for (int bj = blockIdx.x; bj < BQ * NQ; bj += gridDim.x) {
        int cnt = validCnt[bj];
        int b = bj >> 9, j = bj & (NQ - 1);
        if (cnt == 0) {
            if (tid < MID) msgs[(size_t)bj * MID + tid] = BIGNEG;
            continue;
        }
        __syncthreads();   // protect idx_sh from previous iteration's readers
        for (int p = tid; p < cnt; p += 256) idx_sh[p] = validIdx[(size_t)bj * NQ + p];

        const float* msg2b = msg2 + (size_t)(b * NQ) * MID;
        float vmax[2][2] = {{-INFINITY, -INFINITY}, {-INFINITY, -INFINITY}};
        int ntile = (cnt + 127) >> 7;

        for (int t = 0; t < ntile; t++) {
            __syncthreads();   // E smem free (prev mma done / idx_sh written)
            // ---- gather + split-convert 128 rows into E_hi/E_lo ----
            {
                int gi = t * 128 + cvt_r;
                if (gi >= cnt) gi = cnt - 1;
                int i = idx_sh[gi];
                const float4* src = (const float4*)(edge + (((size_t)(b * NQ + i)) * NQ + j) * DN) + cvt_h * 16;
                float4 v[16];
                #pragma unroll
                for (int g = 0; g < 16; g++) v[g] = src[g];
                unsigned rbase = (unsigned)cvt_r * 256u;
                int rx = cvt_r & 7;
                #pragma unroll
                for (int g = 0; g < 8; g++) {
                    float4 v0 = v[2 * g], v1 = v[2 * g + 1];
                    __nv_bfloat162 h0 = __floats2bfloat162_rn(v0.x, v0.y);
                    __nv_bfloat162 h1 = __floats2bfloat162_rn(v0.z, v0.w);
                    __nv_bfloat162 h2 = __floats2bfloat162_rn(v1.x, v1.y);
                    __nv_bfloat162 h3 = __floats2bfloat162_rn(v1.z, v1.w);
                    __nv_bfloat162 e0 = __floats2bfloat162_rn(v0.x - __bfloat162float(h0.x), v0.y - __bfloat162float(h0.y));
                    __nv_bfloat162 e1 = __floats2bfloat162_rn(v0.z - __bfloat162float(h1.x), v0.w - __bfloat162float(h1.y));
                    __nv_bfloat162 e2 = __floats2bfloat162_rn(v1.x - __bfloat162float(h2.x), v1.y - __bfloat162float(h2.y));
                    __nv_bfloat162 e3 = __floats2bfloat162_rn(v1.z - __bfloat162float(h3.x), v1.w - __bfloat162float(h3.y));
                    int kb = cvt_h * 8 + g;
                    unsigned off = rbase + (unsigned)((kb ^ rx) << 4);
                    sts128(sbase + off, pack2(h0), pack2(h1), pack2(h2), pack2(h3));
                    sts128(sbase + 32768 + off, pack2(e0), pack2(e1), pack2(e2), pack2(e3));
                }
            }
            __syncthreads();

            // ---- mma: acc[mt][nt] = E_tile x W^T (3-term split) ----
            float acc[8][2][4];
            #pragma unroll
            for (int mt = 0; mt < 8; mt++)
                #pragma unroll
                for (int nt = 0; nt < 2; nt++) {
                    acc[mt][nt][0] = 0.f; acc[mt][nt][1] = 0.f;
                    acc[mt][nt][2] = 0.f; acc[mt][nt][3] = 0.f;
                }
            #pragma unroll
            for (int kt = 0; kt < 8; kt++) {
                unsigned kb = (unsigned)kt * 2u + akoff;
                #pragma unroll
                for (int mt = 0; mt < 8; mt++) {
                    unsigned ilane = (unsigned)mt * 16u + arow;
                    unsigned aoff = ilane * 256u + ((kb ^ (ilane & 7u)) << 4);
                    unsigned ah[4], al[4];
                    ldmx4(ah, sbase + aoff);
                    ldmx4(al, sbase + 32768 + aoff);
                    #pragma unroll
                    for (int nt = 0; nt < 2; nt++) {
                        mma16816(acc[mt][nt], ah, bhi[kt][nt]);
                        mma16816(acc[mt][nt], ah, blo[kt][nt]);
                        mma16816(acc[mt][nt], al, bhi[kt][nt]);
                    }
                }
            }

            // ---- epilogue: + msg2[i,m], fold into running max ----
            #pragma unroll
            for (int mt = 0; mt < 8; mt++) {
                int r0 = t * 128 + mt * 16 + (l >> 2);
                int r1 = r0 + 8;
                if (r0 >= cnt) r0 = cnt - 1;
                if (r1 >= cnt) r1 = cnt - 1;
                int i0 = idx_sh[r0], i1 = idx_sh[r1];
                #pragma unroll
                for (int nt = 0; nt < 2; nt++) {
                    int c = w * 16 + nt * 8 + (l & 3) * 2;
                    float2 ma = *(const float2*)&msg2b[(size_t)i0 * MID + c];
                    float2 mb = *(const float2*)&msg2b[(size_t)i1 * MID + c];
                    vmax[nt][0] = fmaxf(vmax[nt][0], acc[mt][nt][0] + ma.x);
                    vmax[nt][1] = fmaxf(vmax[nt][1], acc[mt][nt][1] + ma.y);
                    vmax[nt][0] = fmaxf(vmax[nt][0], acc[mt][nt][2] + mb.x);
                    vmax[nt][1] = fmaxf(vmax[nt][1], acc[mt][nt][3] + mb.y);
                }
            }
        }

        // ---- reduce over lanes sharing the same columns (xor 4, 8, 16) ----
        #pragma unroll
        for (int nt = 0; nt < 2; nt++)
            #pragma unroll
            for (int q = 0; q < 2; q++) {
                float v = vmax[nt][q];
                v = fmaxf(v, __shfl_xor_sync(0xffffffffu, v, 4));
                v = fmaxf(v, __shfl_xor_sync(0xffffffffu, v, 8));
                v = fmaxf(v, __shfl_xor_sync(0xffffffffu, v, 16));
                vmax[nt][q] = v;
            }
        if (l < 4) {
            #pragma unroll
            for (int nt = 0; nt < 2; nt++) {
                int m = w * 16 + nt * 8 + l * 2;
                #pragma unroll
                for (int q = 0; q < 2; q++) {
                    msgs[(size_t)bj * MID + m + q] =
                        msg1[(size_t)bj * MID + m + q] + msgg[b * MID + m + q]
                        + me_b[m + q] + vmax[nt][q];
                }
            }
        }
    }
}

// ---------------- launch ----------------
extern "C" void kernel_launch(void* const* d_in, const int* in_sizes, int n_in,
                              void* d_out, int out_size) {
    const float* node   = (const float*)d_in[0];
    const float* edge   = (const float*)d_in[1];
    const float* graph  = (const float*)d_in[2];
    const float* hidden = (const float*)d_in[3];
    const int*   adj    = (const int*)d_in[4];
    const float* m1_w = (const float*)d_in[5];
    const float* m1_b = (const float*)d_in[6];
    const float* m2_w = (const float*)d_in[7];
    const float* m2_b = (const float*)d_in[8];
    const float* me_w = (const float*)d_in[9];
    const float* me_b = (const float*)d_in[10];
    const float* mg_w = (const float*)d_in[11];
    const float* mg_b = (const float*)d_in[12];
    const float* o1_w = (const float*)d_in[13];
    const float* o1_b = (const float*)d_in[14];
    const float* o2_w = (const float*)d_in[15];
    const float* o2_b = (const float*)d_in[16];

    float *z, *msg1, *msg2, *h1, *msgs, *msgg;
    unsigned short* vidx;
    int* vcnt;
    __nv_bfloat16 *wth, *wtl;
    cudaGetSymbolAddress((void**)&z, g_z);
    cudaGetSymbolAddress((void**)&msg1, g_msg1);
    cudaGetSymbolAddress((void**)&msg2, g_msg2);
    cudaGetSymbolAddress((void**)&h1, g_h1);
    cudaGetSymbolAddress((void**)&msgs, g_msgs);
    cudaGetSymbolAddress((void**)&msgg, g_msgg);
    cudaGetSymbolAddress((void**)&vidx, g_validIdx);
    cudaGetSymbolAddress((void**)&vcnt, g_validCnt);
    cudaGetSymbolAddress((void**)&wth, g_wt_hi);
    cudaGetSymbolAddress((void**)&wtl, g_wt_lo);

    cudaFuncSetAttribute(edge_mma_kernel,
                         cudaFuncAttributeMaxDynamicSharedMemorySize, EDGE_SMEM);

    concat_z_kernel<<<(BQ * NQ * ZIN) / 256, 256>>>(node, hidden, z);
    compact_kernel<<<(BQ * NQ) / 8, 256>>>(adj, vidx, vcnt);
    prep_wt_kernel<<<(NLAYER * MID * DN) / 256, 256>>>(me_w, wth, wtl);

    for (int l = 0; l < NLAYER; l++) {
        zmm_kernel<<<dim3(8, (BQ * NQ) / 64), 256>>>(
            z,
            m1_w + (size_t)l * ZIN * MID, m1_b + l * MID,
            m2_w + (size_t)l * ZIN * MID, m2_b + l * MID,
            o1_w + (size_t)l * ZIN * OUT, o1_b + l * OUT,
            msg1, msg2, h1);
        msgg_kernel<<<BQ, MID>>>(graph, mg_w + (size_t)l * DN * MID, mg_b + l * MID, msgg);

        edge_mma_kernel<<<148, 256, EDGE_SMEM>>>(
            edge, wth + (size_t)l * MID * DN, wtl + (size_t)l * MID * DN,
            me_b + l * MID, msg1, msg2, msgg, vidx, vcnt, msgs);

        float* dest = (l == NLAYER - 1) ? (float*)d_out : z;
        o2_kernel<<<dim3(OUT / 64, (BQ * NQ) / 64), 256>>>(
            msgs, o2_w + (size_t)l * MID * OUT, o2_b + l * OUT, h1, dest);
    }
}

// round 5
// speedup vs baseline: 2.5413x; 1.4107x over previous
#include <cuda_runtime.h>
#include <cuda_bf16.h>
#include <cuda_fp16.h>
#include <cstdint>

#define BQ 2
#define NQ 512
#define DN 128
#define MID 128
#define ZIN 256
#define OUT 256
#define NLAYER 2
#define BIGNEG (-1e6f)

// ---------------- scratch ----------------
__device__ float g_z[BQ*NQ*ZIN];
__device__ float g_msg1[BQ*NQ*MID];
__device__ float g_msg2[BQ*NQ*MID];
__device__ float g_h1[BQ*NQ*OUT];
__device__ float g_msgs[BQ*NQ*MID];
__device__ float g_msgg[BQ*MID];
__device__ unsigned short g_validIdx[BQ*NQ*NQ];
__device__ int g_validCnt[BQ*NQ];
__device__ __align__(16) __half g_wt_h[NLAYER*MID*DN];   // me_w^T fp16 [l][m][d]

// ---------------- helpers ----------------
__device__ __forceinline__ unsigned smem_u32(const void* p) {
    return (unsigned)__cvta_generic_to_shared(p);
}
__device__ __forceinline__ void cp_async16(void* s, const void* g) {
    asm volatile("cp.async.ca.shared.global [%0], [%1], 16;" :: "r"(smem_u32(s)), "l"(g));
}
__device__ __forceinline__ void cp_async16u(unsigned s, const void* g) {
    asm volatile("cp.async.ca.shared.global [%0], [%1], 16;" :: "r"(s), "l"(g));
}
__device__ __forceinline__ void cp_commit() { asm volatile("cp.async.commit_group;"); }
template <int K>
__device__ __forceinline__ void cp_wait() { asm volatile("cp.async.wait_group %0;" :: "n"(K)); }

__device__ __forceinline__ void ldmx4(unsigned* a, unsigned addr) {
    asm volatile("ldmatrix.sync.aligned.m8n8.x4.shared.b16 {%0,%1,%2,%3}, [%4];"
                 : "=r"(a[0]), "=r"(a[1]), "=r"(a[2]), "=r"(a[3]) : "r"(addr));
}
__device__ __forceinline__ void mma16816(float* d, const unsigned* a, const unsigned* b) {
    asm volatile(
        "mma.sync.aligned.m16n8k16.row.col.f32.f16.f16.f32 "
        "{%0,%1,%2,%3}, {%4,%5,%6,%7}, {%8,%9}, {%0,%1,%2,%3};"
        : "+f"(d[0]), "+f"(d[1]), "+f"(d[2]), "+f"(d[3])
        : "r"(a[0]), "r"(a[1]), "r"(a[2]), "r"(a[3]), "r"(b[0]), "r"(b[1]));
}
__device__ __forceinline__ void sts128(unsigned a, unsigned x, unsigned y, unsigned z, unsigned w) {
    asm volatile("st.shared.v4.b32 [%0], {%1,%2,%3,%4};" :: "r"(a), "r"(x), "r"(y), "r"(z), "r"(w) : "memory");
}
__device__ __forceinline__ unsigned packh2(float a, float b) {
    __half2 h = __floats2half2_rn(a, b);
    return *(unsigned*)&h;
}

// ---------------- prep kernels ----------------
__global__ void concat_z_kernel(const float* __restrict__ node,
                                const float* __restrict__ hidden,
                                float* __restrict__ z) {
    int idx = blockIdx.x * blockDim.x + threadIdx.x;
    int c = idx & (ZIN - 1);
    int row = idx >> 8;
    z[idx] = (c < DN) ? node[row * DN + c] : hidden[row * DN + (c - DN)];
}

__global__ void compact_kernel(const int* __restrict__ adj,
                               unsigned short* __restrict__ idxOut,
                               int* __restrict__ cntOut) {
    int gwarp = (blockIdx.x * blockDim.x + threadIdx.x) >> 5;
    int lane = threadIdx.x & 31;
    if (gwarp >= BQ * NQ) return;
    int b = gwarp / NQ, j = gwarp % NQ;
    int base = gwarp * NQ;
    int cnt = 0;
    for (int it = 0; it < NQ / 32; it++) {
        int i = it * 32 + lane;
        int v = adj[((size_t)(b * NQ + i)) * NQ + j];
        unsigned mm = __ballot_sync(0xffffffffu, v != 0);
        if (v != 0) idxOut[base + cnt + __popc(mm & ((1u << lane) - 1u))] = (unsigned short)i;
        cnt += __popc(mm);
    }
    if (lane == 0) cntOut[gwarp] = cnt;
}

__global__ void prep_wt_kernel(const float* __restrict__ me_w,
                               __half* __restrict__ wt_h) {
    int idx = blockIdx.x * blockDim.x + threadIdx.x;   // L*128*128
    int l = idx >> 14;
    int r = idx & 16383;
    int m = r >> 7, d = r & 127;
    wt_h[idx] = __float2half_rn(me_w[(size_t)l * DN * MID + d * MID + m]);
}

__global__ void msgg_kernel(const float* __restrict__ graph,
                            const float* __restrict__ w,
                            const float* __restrict__ bias,
                            float* __restrict__ out) {
    int b = blockIdx.x;
    int m = threadIdx.x;
    __shared__ float gsh[DN];
    gsh[m] = graph[b * DN + m];
    __syncthreads();
    float s = bias[m];
    #pragma unroll 8
    for (int d = 0; d < DN; d++) s += gsh[d] * w[d * MID + m];
    out[b * MID + m] = s;
}

// ---------------- pipelined 64x64 fp32 GEMM body (small GEMMs) ----------------
__device__ __forceinline__ void gemm64(
    const float* __restrict__ A, const float* __restrict__ W,
    const float* __restrict__ bias, const float* __restrict__ addsrc,
    float* __restrict__ C, int K, int Nw, int rowBase, int cb, int relu,
    float (&As)[2][64][20], float (&Bs)[2][16][64]) {
    int tid = threadIdx.x;
    int tx = tid & 15, ty = tid >> 4;
    int ar = tid >> 2, ak = (tid & 3) * 4;
    int bk = tid >> 4, bc = (tid & 15) * 4;
    float acc[4][4] = {};
    int nkt = K >> 4;
    cp_async16(&As[0][ar][ak], &A[(size_t)(rowBase + ar) * K + ak]);
    cp_async16(&Bs[0][bk][bc], &W[(size_t)bk * Nw + cb + bc]);
    cp_commit();
    for (int kt = 0; kt < nkt; kt++) {
        int buf = kt & 1;
        if (kt + 1 < nkt) {
            cp_async16(&As[buf ^ 1][ar][ak], &A[(size_t)(rowBase + ar) * K + (kt + 1) * 16 + ak]);
            cp_async16(&Bs[buf ^ 1][bk][bc], &W[(size_t)((kt + 1) * 16 + bk) * Nw + cb + bc]);
            cp_commit();
            cp_wait<1>();
        } else {
            cp_wait<0>();
        }
        __syncthreads();
        #pragma unroll
        for (int k = 0; k < 16; k++) {
            float a0 = As[buf][ty * 4 + 0][k];
            float a1 = As[buf][ty * 4 + 1][k];
            float a2 = As[buf][ty * 4 + 2][k];
            float a3 = As[buf][ty * 4 + 3][k];
            float4 bv = *(const float4*)&Bs[buf][k][tx * 4];
            acc[0][0] += a0 * bv.x; acc[0][1] += a0 * bv.y; acc[0][2] += a0 * bv.z; acc[0][3] += a0 * bv.w;
            acc[1][0] += a1 * bv.x; acc[1][1] += a1 * bv.y; acc[1][2] += a1 * bv.z; acc[1][3] += a1 * bv.w;
            acc[2][0] += a2 * bv.x; acc[2][1] += a2 * bv.y; acc[2][2] += a2 * bv.z; acc[2][3] += a2 * bv.w;
            acc[3][0] += a3 * bv.x; acc[3][1] += a3 * bv.y; acc[3][2] += a3 * bv.z; acc[3][3] += a3 * bv.w;
        }
        __syncthreads();
    }
    #pragma unroll
    for (int i2 = 0; i2 < 4; i2++) {
        int row = rowBase + ty * 4 + i2;
        #pragma unroll
        for (int j2 = 0; j2 < 4; j2++) {
            int col = cb + tx * 4 + j2;
            float v = acc[i2][j2] + bias[col];
            if (addsrc) v += addsrc[(size_t)row * Nw + col];
            if (relu) v = fmaxf(v, 0.0f);
            C[(size_t)row * Nw + col] = v;
        }
    }
}

__global__ __launch_bounds__(256) void zmm_kernel(
    const float* __restrict__ z,
    const float* __restrict__ m1_w, const float* __restrict__ m1_b,
    const float* __restrict__ m2_w, const float* __restrict__ m2_b,
    const float* __restrict__ o1_w, const float* __restrict__ o1_b,
    float* __restrict__ msg1, float* __restrict__ msg2, float* __restrict__ h1) {
    __shared__ float As[2][64][20];
    __shared__ float Bs[2][16][64];
    int bx = blockIdx.x, rb = blockIdx.y * 64;
    if (bx < 2)      gemm64(z, m1_w, m1_b, nullptr, msg1, 256, 128, rb, bx * 64, 0, As, Bs);
    else if (bx < 4) gemm64(z, m2_w, m2_b, nullptr, msg2, 256, 128, rb, (bx - 2) * 64, 0, As, Bs);
    else             gemm64(z, o1_w, o1_b, nullptr, h1, 256, 256, rb, (bx - 4) * 64, 0, As, Bs);
}

__global__ __launch_bounds__(256) void o2_kernel(
    const float* __restrict__ msgs, const float* __restrict__ W,
    const float* __restrict__ bias, const float* __restrict__ h1,
    float* __restrict__ C) {
    __shared__ float As[2][64][20];
    __shared__ float Bs[2][16][64];
    gemm64(msgs, W, bias, h1, C, 128, 256, blockIdx.y * 64, blockIdx.x * 64, 1, As, Bs);
}

// ---------------- fused edge GEMM + masked max via fp16 mma.sync ----------------
// smem: [0,32768) E tile fp16 swizzled (also W staging area), [32768,33792) idx
#define EDGE_SMEM 33792
#define EDGE_GRID 296

__global__ __launch_bounds__(256, 2) void edge_mma_kernel(
    const float* __restrict__ edge,
    const __half* __restrict__ wt_h,
    const float* __restrict__ me_b,
    const float* __restrict__ msg1, const float* __restrict__ msg2,
    const float* __restrict__ msgg,
    const unsigned short* __restrict__ validIdx, const int* __restrict__ validCnt,
    float* __restrict__ msgs) {
    extern __shared__ char smraw[];
    unsigned sbase = smem_u32(smraw);
    unsigned short* idx_sh = (unsigned short*)(smraw + 32768);

    int tid = threadIdx.x;
    int w = tid >> 5, l = tid & 31;

    // ---- stage W^T fp16 (32KB) into E area, read B fragments, then release ----
    #pragma unroll
    for (int u = 0; u < 8; u++) {
        int q = tid + u * 256;                 // 16B unit 0..2047
        cp_async16u(sbase + q * 16, (const char*)wt_h + q * 16);
    }
    cp_commit();
    cp_wait<0>();
    __syncthreads();

    // B frag: lane l holds W[n][k..k+1], n = w*16 + nt*8 + l/4, k = kt*16 + (l%4)*2 (+8 for reg1)
    unsigned bh[8][2][2];
    {
        int nl = l >> 2, k4 = (l & 3) * 4;
        #pragma unroll
        for (int nt = 0; nt < 2; nt++) {
            unsigned roff = (unsigned)(w * 16 + nt * 8 + nl) * 256u + (unsigned)k4;
            #pragma unroll
            for (int kt = 0; kt < 8; kt++) {
                bh[kt][nt][0] = *(const unsigned*)(smraw + roff + kt * 32);
                bh[kt][nt][1] = *(const unsigned*)(smraw + roff + kt * 32 + 16);
            }
        }
    }
    __syncthreads();   // W area now reusable as E tile

    int cvt_r = tid >> 1, cvt_h = tid & 1;     // 2 threads per row
    unsigned arow = (unsigned)(l & 15);
    unsigned akoff = (unsigned)(l >> 4);
    int rx = cvt_r & 7;

    for (int bj = blockIdx.x; bj < BQ * NQ; bj += gridDim.x) {
        int cnt = validCnt[bj];
        int b = bj >> 9, j = bj & (NQ - 1);
        if (cnt == 0) {
            if (tid < MID) msgs[(size_t)bj * MID + tid] = BIGNEG;
            continue;
        }
        __syncthreads();   // protect idx_sh from previous iteration
        for (int p = tid; p < cnt; p += 256) idx_sh[p] = validIdx[(size_t)bj * NQ + p];

        const float* msg2b = msg2 + (size_t)(b * NQ) * MID;
        float vmax[2][2] = {{-INFINITY, -INFINITY}, {-INFINITY, -INFINITY}};
        int ntile = (cnt + 127) >> 7;

        for (int t = 0; t < ntile; t++) {
            __syncthreads();   // E smem free
            // ---- gather + fp16 convert 128 rows (2 rounds of 8 float4) ----
            {
                int gi = t * 128 + cvt_r;
                if (gi >= cnt) gi = cnt - 1;
                int i = idx_sh[gi];
                const float4* src = (const float4*)(edge + (((size_t)(b * NQ + i)) * NQ + j) * DN) + cvt_h * 16;
                unsigned rbase = (unsigned)cvt_r * 256u;
                #pragma unroll
                for (int p = 0; p < 2; p++) {
                    float4 v[8];
                    #pragma unroll
                    for (int g = 0; g < 8; g++) v[g] = src[p * 8 + g];
                    #pragma unroll
                    for (int s = 0; s < 4; s++) {
                        float4 v0 = v[2 * s], v1 = v[2 * s + 1];
                        int kb = cvt_h * 8 + p * 4 + s;          // 16B-chunk index (8 halves)
                        unsigned off = rbase + (unsigned)((kb ^ rx) << 4);
                        sts128(sbase + off,
                               packh2(v0.x, v0.y), packh2(v0.z, v0.w),
                               packh2(v1.x, v1.y), packh2(v1.z, v1.w));
                    }
                }
            }
            __syncthreads();

            // ---- mma: acc = E_tile x W^T ----
            float acc[8][2][4];
            #pragma unroll
            for (int mt = 0; mt < 8; mt++)
                #pragma unroll
                for (int nt = 0; nt < 2; nt++) {
                    acc[mt][nt][0] = 0.f; acc[mt][nt][1] = 0.f;
                    acc[mt][nt][2] = 0.f; acc[mt][nt][3] = 0.f;
                }
            #pragma unroll
            for (int kt = 0; kt < 8; kt++) {
                unsigned kb = (unsigned)kt * 2u + akoff;
                #pragma unroll
                for (int mt = 0; mt < 8; mt++) {
                    unsigned ilane = (unsigned)mt * 16u + arow;
                    unsigned aoff = ilane * 256u + ((kb ^ (ilane & 7u)) << 4);
                    unsigned ah[4];
                    ldmx4(ah, sbase + aoff);
                    #pragma unroll
                    for (int nt = 0; nt < 2; nt++) mma16816(acc[mt][nt], ah, bh[kt][nt]);
                }
            }

            // ---- epilogue: + msg2[i,m], fold into running max ----
            #pragma unroll
            for (int mt = 0; mt < 8; mt++) {
                int r0 = t * 128 + mt * 16 + (l >> 2);
                int r1 = r0 + 8;
                if (r0 >= cnt) r0 = cnt - 1;
                if (r1 >= cnt) r1 = cnt - 1;
                int i0 = idx_sh[r0], i1 = idx_sh[r1];
                #pragma unroll
                for (int nt = 0; nt < 2; nt++) {
                    int c = w * 16 + nt * 8 + (l & 3) * 2;
                    float2 ma = *(const float2*)&msg2b[(size_t)i0 * MID + c];
                    float2 mb = *(const float2*)&msg2b[(size_t)i1 * MID + c];
                    vmax[nt][0] = fmaxf(vmax[nt][0], acc[mt][nt][0] + ma.x);
                    vmax[nt][1] = fmaxf(vmax[nt][1], acc[mt][nt][1] + ma.y);
                    vmax[nt][0] = fmaxf(vmax[nt][0], acc[mt][nt][2] + mb.x);
                    vmax[nt][1] = fmaxf(vmax[nt][1], acc[mt][nt][3] + mb.y);
                }
            }
        }

        // ---- reduce over lanes sharing the same columns ----
        #pragma unroll
        for (int nt = 0; nt < 2; nt++)
            #pragma unroll
            for (int q = 0; q < 2; q++) {
                float v = vmax[nt][q];
                v = fmaxf(v, __shfl_xor_sync(0xffffffffu, v, 4));
                v = fmaxf(v, __shfl_xor_sync(0xffffffffu, v, 8));
                v = fmaxf(v, __shfl_xor_sync(0xffffffffu, v, 16));
                vmax[nt][q] = v;
            }
        if (l < 4) {
            #pragma unroll
            for (int nt = 0; nt < 2; nt++) {
                int m = w * 16 + nt * 8 + l * 2;
                #pragma unroll
                for (int q = 0; q < 2; q++) {
                    msgs[(size_t)bj * MID + m + q] =
                        msg1[(size_t)bj * MID + m + q] + msgg[b * MID + m + q]
                        + me_b[m + q] + vmax[nt][q];
                }
            }
        }
    }
}

// ---------------- launch ----------------
extern "C" void kernel_launch(void* const* d_in, const int* in_sizes, int n_in,
                              void* d_out, int out_size) {
    const float* node   = (const float*)d_in[0];
    const float* edge   = (const float*)d_in[1];
    const float* graph  = (const float*)d_in[2];
    const float* hidden = (const float*)d_in[3];
    const int*   adj    = (const int*)d_in[4];
    const float* m1_w = (const float*)d_in[5];
    const float* m1_b = (const float*)d_in[6];
    const float* m2_w = (const float*)d_in[7];
    const float* m2_b = (const float*)d_in[8];
    const float* me_w = (const float*)d_in[9];
    const float* me_b = (const float*)d_in[10];
    const float* mg_w = (const float*)d_in[11];
    const float* mg_b = (const float*)d_in[12];
    const float* o1_w = (const float*)d_in[13];
    const float* o1_b = (const float*)d_in[14];
    const float* o2_w = (const float*)d_in[15];
    const float* o2_b = (const float*)d_in[16];

    float *z, *msg1, *msg2, *h1, *msgs, *msgg;
    unsigned short* vidx;
    int* vcnt;
    __half* wth;
    cudaGetSymbolAddress((void**)&z, g_z);
    cudaGetSymbolAddress((void**)&msg1, g_msg1);
    cudaGetSymbolAddress((void**)&msg2, g_msg2);
    cudaGetSymbolAddress((void**)&h1, g_h1);
    cudaGetSymbolAddress((void**)&msgs, g_msgs);
    cudaGetSymbolAddress((void**)&msgg, g_msgg);
    cudaGetSymbolAddress((void**)&vidx, g_validIdx);
    cudaGetSymbolAddress((void**)&vcnt, g_validCnt);
    cudaGetSymbolAddress((void**)&wth, g_wt_h);

    cudaFuncSetAttribute(edge_mma_kernel,
                         cudaFuncAttributeMaxDynamicSharedMemorySize, EDGE_SMEM);

    concat_z_kernel<<<(BQ * NQ * ZIN) / 256, 256>>>(node, hidden, z);
    compact_kernel<<<(BQ * NQ) / 8, 256>>>(adj, vidx, vcnt);
    prep_wt_kernel<<<(NLAYER * MID * DN) / 256, 256>>>(me_w, wth);

    for (int l = 0; l < NLAYER; l++) {
        zmm_kernel<<<dim3(8, (BQ * NQ) / 64), 256>>>(
            z,
            m1_w + (size_t)l * ZIN * MID, m1_b + l * MID,
            m2_w + (size_t)l * ZIN * MID, m2_b + l * MID,
            o1_w + (size_t)l * ZIN * OUT, o1_b + l * OUT,
            msg1, msg2, h1);
        msgg_kernel<<<BQ, MID>>>(graph, mg_w + (size_t)l * DN * MID, mg_b + l * MID, msgg);

        edge_mma_kernel<<<EDGE_GRID, 256, EDGE_SMEM>>>(
            edge, wth + (size_t)l * MID * DN,
            me_b + l * MID, msg1, msg2, msgg, vidx, vcnt, msgs);

        float* dest = (l == NLAYER - 1) ? (float*)d_out : z;
        o2_kernel<<<dim3(OUT / 64, (BQ * NQ) / 64), 256>>>(
            msgs, o2_w + (size_t)l * MID * OUT, o2_b + l * OUT, h1, dest);
    }
}